// round 1
// baseline (speedup 1.0000x reference)
#include <cuda_runtime.h>

#define DIMSZ 768
#define NTOK 1024
#define BATCH 8
#define HEADS 12
#define DH 64
#define NROWS (BATCH * NTOK)      /* 8192 */
#define QKVN (3 * DIMSZ)          /* 2304 */
#define SCALE 0.125f              /* DH^-0.5 */

#define QP 65                     /* pad for Q/K/P tiles */
#define VP 68                     /* pad for V tile (float4-aligned rows) */

// Scratch (device globals: allocation-free)
__device__ float g_xn[NROWS * DIMSZ];
__device__ float g_qkv[NROWS * QKVN];
__device__ float g_att[NROWS * DIMSZ];

// ---------------------------------------------------------------------------
// LayerNorm: one block per row of 768
// ---------------------------------------------------------------------------
__global__ __launch_bounds__(256) void ln_kernel(const float* __restrict__ x,
                                                 const float* __restrict__ gamma,
                                                 const float* __restrict__ beta,
                                                 float* __restrict__ y) {
    int row = blockIdx.x;
    int t = threadIdx.x;
    const float* xr = x + (size_t)row * DIMSZ;
    float v0 = xr[t], v1 = xr[t + 256], v2 = xr[t + 512];
    float s = v0 + v1 + v2;
    float ss = v0 * v0 + v1 * v1 + v2 * v2;
#pragma unroll
    for (int o = 16; o > 0; o >>= 1) {
        s += __shfl_xor_sync(0xffffffffu, s, o);
        ss += __shfl_xor_sync(0xffffffffu, ss, o);
    }
    __shared__ float sb[8], ssb[8];
    __shared__ float smu, srstd;
    if ((t & 31) == 0) { sb[t >> 5] = s; ssb[t >> 5] = ss; }
    __syncthreads();
    if (t == 0) {
        float S = 0.f, SS = 0.f;
#pragma unroll
        for (int i = 0; i < 8; i++) { S += sb[i]; SS += ssb[i]; }
        float mu = S * (1.0f / DIMSZ);
        float var = SS * (1.0f / DIMSZ) - mu * mu;
        smu = mu;
        srstd = rsqrtf(var + 1e-5f);
    }
    __syncthreads();
    float mu = smu, rstd = srstd;
    float* yr = y + (size_t)row * DIMSZ;
    yr[t]       = (v0 - mu) * rstd * gamma[t]       + beta[t];
    yr[t + 256] = (v1 - mu) * rstd * gamma[t + 256] + beta[t + 256];
    yr[t + 512] = (v2 - mu) * rstd * gamma[t + 512] + beta[t + 512];
}

// ---------------------------------------------------------------------------
// SGEMM: C[M,N] = A[M,K] @ B[K,N] (+ bias). BM=128, BN=64, BK=16, 256 thr,
// 8x4 micro-tile per thread. M%128==0, N%64==0, K%16==0 assumed.
// ---------------------------------------------------------------------------
template <bool HAS_BIAS>
__global__ __launch_bounds__(256) void sgemm_kernel(const float* __restrict__ A,
                                                    const float* __restrict__ B,
                                                    const float* __restrict__ bias,
                                                    float* __restrict__ C,
                                                    int M, int N, int K) {
    __shared__ float As[16 * 132];   // transposed: As[k][m], pad 132
    __shared__ float Bs[16 * 64];    // Bs[k][n]
    int t = threadIdx.x;
    int tx = t & 15, ty = t >> 4;
    int m0 = blockIdx.y * 128, n0 = blockIdx.x * 64;

    float acc[8][4];
#pragma unroll
    for (int r = 0; r < 8; r++)
#pragma unroll
        for (int c = 0; c < 4; c++) acc[r][c] = 0.f;

    int arow = t >> 2;     // 0..63
    int ac4 = t & 3;       // 0..3   (k-quad)
    int brow = t >> 4;     // 0..15
    int bc4 = t & 15;      // 0..15  (n-quad)

    for (int k0 = 0; k0 < K; k0 += 16) {
        float4 av0 = *(const float4*)&A[(size_t)(m0 + arow) * K + k0 + ac4 * 4];
        float4 av1 = *(const float4*)&A[(size_t)(m0 + arow + 64) * K + k0 + ac4 * 4];
        float4 bv  = *(const float4*)&B[(size_t)(k0 + brow) * N + n0 + bc4 * 4];
        __syncthreads();
        As[(ac4 * 4 + 0) * 132 + arow] = av0.x;
        As[(ac4 * 4 + 1) * 132 + arow] = av0.y;
        As[(ac4 * 4 + 2) * 132 + arow] = av0.z;
        As[(ac4 * 4 + 3) * 132 + arow] = av0.w;
        As[(ac4 * 4 + 0) * 132 + arow + 64] = av1.x;
        As[(ac4 * 4 + 1) * 132 + arow + 64] = av1.y;
        As[(ac4 * 4 + 2) * 132 + arow + 64] = av1.z;
        As[(ac4 * 4 + 3) * 132 + arow + 64] = av1.w;
        *(float4*)&Bs[brow * 64 + bc4 * 4] = bv;
        __syncthreads();
#pragma unroll
        for (int k = 0; k < 16; k++) {
            float4 a0 = *(const float4*)&As[k * 132 + ty * 8];
            float4 a1 = *(const float4*)&As[k * 132 + ty * 8 + 4];
            float4 b4 = *(const float4*)&Bs[k * 64 + tx * 4];
            float av[8] = {a0.x, a0.y, a0.z, a0.w, a1.x, a1.y, a1.z, a1.w};
            float bb[4] = {b4.x, b4.y, b4.z, b4.w};
#pragma unroll
            for (int r = 0; r < 8; r++)
#pragma unroll
                for (int c = 0; c < 4; c++) acc[r][c] += av[r] * bb[c];
        }
    }

    float4 bias4 = make_float4(0.f, 0.f, 0.f, 0.f);
    if (HAS_BIAS) bias4 = *(const float4*)&bias[n0 + tx * 4];
#pragma unroll
    for (int r = 0; r < 8; r++) {
        float4 o = make_float4(acc[r][0] + bias4.x, acc[r][1] + bias4.y,
                               acc[r][2] + bias4.z, acc[r][3] + bias4.w);
        *(float4*)&C[(size_t)(m0 + ty * 8 + r) * N + n0 + tx * 4] = o;
    }
}

// ---------------------------------------------------------------------------
// Flash-style attention with relative position bias.
// Block = 64 q-rows for one (b,h). Tiles of 64 keys. Online softmax, stats in
// registers (each row owned by a 16-lane group; shfl-reduced).
// ---------------------------------------------------------------------------
__global__ __launch_bounds__(256) void attn_kernel(const float* __restrict__ qkv,
                                                   const float* __restrict__ rpb,
                                                   float* __restrict__ out) {
    extern __shared__ float sm[];
    float* Qs = sm;                 // 64 x QP
    float* Ks = Qs + 64 * QP;       // 64 x QP
    float* Ps = Ks + 64 * QP;       // 64 x QP
    float* Vs = Ps + 64 * QP;       // 64 x VP

    int t = threadIdx.x;
    int tx = t & 15, ty = t >> 4;
    int b = blockIdx.z, h = blockIdx.y;
    int i0 = blockIdx.x * 64;

    const float* qbase = qkv + (size_t)b * NTOK * QKVN + h * DH;
    const float* kbase = qbase + DIMSZ;
    const float* vbase = qbase + 2 * DIMSZ;
    const float* biasb = rpb + ((size_t)h * NTOK + i0) * NTOK;

    // Load Q tile [64 x 64]
#pragma unroll
    for (int i = 0; i < 4; i++) {
        int f = t + i * 256;
        int row = f >> 4, c4 = f & 15;
        float4 v = *(const float4*)&qbase[(size_t)(i0 + row) * QKVN + c4 * 4];
        float* dst = &Qs[row * QP + c4 * 4];
        dst[0] = v.x; dst[1] = v.y; dst[2] = v.z; dst[3] = v.w;
    }

    float acc[4][4];
    float mrow[4], lrow[4];
#pragma unroll
    for (int r = 0; r < 4; r++) {
        mrow[r] = -1e30f;
        lrow[r] = 0.f;
#pragma unroll
        for (int c = 0; c < 4; c++) acc[r][c] = 0.f;
    }

    const int qrow = ty * 4 * QP;
    const int krow = tx * 4 * QP;

    for (int j0 = 0; j0 < NTOK; j0 += 64) {
        __syncthreads();  // previous iteration done with Ks/Vs/Ps (also covers Q load)
        // Load K,V tiles [64 x 64]
#pragma unroll
        for (int i = 0; i < 4; i++) {
            int f = t + i * 256;
            int row = f >> 4, c4 = f & 15;
            float4 kv = *(const float4*)&kbase[(size_t)(j0 + row) * QKVN + c4 * 4];
            float* kd = &Ks[row * QP + c4 * 4];
            kd[0] = kv.x; kd[1] = kv.y; kd[2] = kv.z; kd[3] = kv.w;
            float4 vv = *(const float4*)&vbase[(size_t)(j0 + row) * QKVN + c4 * 4];
            *(float4*)&Vs[row * VP + c4 * 4] = vv;
        }
        __syncthreads();

        // S = Q @ K^T   (4x4 per thread)
        float s[4][4];
#pragma unroll
        for (int r = 0; r < 4; r++)
#pragma unroll
            for (int c = 0; c < 4; c++) s[r][c] = 0.f;
#pragma unroll 16
        for (int d = 0; d < DH; d++) {
            float a0 = Qs[qrow + d];
            float a1 = Qs[qrow + QP + d];
            float a2 = Qs[qrow + 2 * QP + d];
            float a3 = Qs[qrow + 3 * QP + d];
            float b0 = Ks[krow + d];
            float b1 = Ks[krow + QP + d];
            float b2 = Ks[krow + 2 * QP + d];
            float b3 = Ks[krow + 3 * QP + d];
            s[0][0] += a0 * b0; s[0][1] += a0 * b1; s[0][2] += a0 * b2; s[0][3] += a0 * b3;
            s[1][0] += a1 * b0; s[1][1] += a1 * b1; s[1][2] += a1 * b2; s[1][3] += a1 * b3;
            s[2][0] += a2 * b0; s[2][1] += a2 * b1; s[2][2] += a2 * b2; s[2][3] += a2 * b3;
            s[3][0] += a3 * b0; s[3][1] += a3 * b1; s[3][2] += a3 * b2; s[3][3] += a3 * b3;
        }

        // scale + bias; online softmax per row
#pragma unroll
        for (int r = 0; r < 4; r++) {
            float4 b4 = *(const float4*)&biasb[(size_t)(ty * 4 + r) * NTOK + j0 + tx * 4];
            s[r][0] = s[r][0] * SCALE + b4.x;
            s[r][1] = s[r][1] * SCALE + b4.y;
            s[r][2] = s[r][2] * SCALE + b4.z;
            s[r][3] = s[r][3] * SCALE + b4.w;

            float tmax = fmaxf(fmaxf(s[r][0], s[r][1]), fmaxf(s[r][2], s[r][3]));
#pragma unroll
            for (int o = 8; o > 0; o >>= 1)
                tmax = fmaxf(tmax, __shfl_xor_sync(0xffffffffu, tmax, o));
            float newm = fmaxf(mrow[r], tmax);
            float p0 = __expf(s[r][0] - newm);
            float p1 = __expf(s[r][1] - newm);
            float p2 = __expf(s[r][2] - newm);
            float p3 = __expf(s[r][3] - newm);
            float tsum = p0 + p1 + p2 + p3;
#pragma unroll
            for (int o = 8; o > 0; o >>= 1)
                tsum += __shfl_xor_sync(0xffffffffu, tsum, o);
            float factor = __expf(mrow[r] - newm);
            lrow[r] = lrow[r] * factor + tsum;
            mrow[r] = newm;
            acc[r][0] *= factor; acc[r][1] *= factor;
            acc[r][2] *= factor; acc[r][3] *= factor;
            float* pd = &Ps[(ty * 4 + r) * QP + tx * 4];
            pd[0] = p0; pd[1] = p1; pd[2] = p2; pd[3] = p3;
        }
        __syncthreads();

        // O += P @ V
#pragma unroll 16
        for (int j = 0; j < 64; j++) {
            float4 vv = *(const float4*)&Vs[j * VP + tx * 4];
            float p0 = Ps[qrow + j];
            float p1 = Ps[qrow + QP + j];
            float p2 = Ps[qrow + 2 * QP + j];
            float p3 = Ps[qrow + 3 * QP + j];
            acc[0][0] += p0 * vv.x; acc[0][1] += p0 * vv.y; acc[0][2] += p0 * vv.z; acc[0][3] += p0 * vv.w;
            acc[1][0] += p1 * vv.x; acc[1][1] += p1 * vv.y; acc[1][2] += p1 * vv.z; acc[1][3] += p1 * vv.w;
            acc[2][0] += p2 * vv.x; acc[2][1] += p2 * vv.y; acc[2][2] += p2 * vv.z; acc[2][3] += p2 * vv.w;
            acc[3][0] += p3 * vv.x; acc[3][1] += p3 * vv.y; acc[3][2] += p3 * vv.z; acc[3][3] += p3 * vv.w;
        }
    }

    // epilogue: normalize, write [b, i, h*64 + d]
    float* ob = out + ((size_t)(b * NTOK + i0)) * DIMSZ + h * DH;
#pragma unroll
    for (int r = 0; r < 4; r++) {
        float inv = 1.0f / lrow[r];
        float4 o = make_float4(acc[r][0] * inv, acc[r][1] * inv,
                               acc[r][2] * inv, acc[r][3] * inv);
        *(float4*)&ob[(size_t)(ty * 4 + r) * DIMSZ + tx * 4] = o;
    }
}

// ---------------------------------------------------------------------------
extern "C" void kernel_launch(void* const* d_in, const int* in_sizes, int n_in,
                              void* d_out, int out_size) {
    const float* x    = (const float*)d_in[0];
    const float* rpb  = (const float*)d_in[1];
    const float* Wqkv = (const float*)d_in[2];
    const float* Wout = (const float*)d_in[3];
    const float* bout = (const float*)d_in[4];
    const float* lng  = (const float*)d_in[5];
    const float* lnb  = (const float*)d_in[6];
    float* out = (float*)d_out;

    float *xn, *qkvp, *attp;
    cudaGetSymbolAddress((void**)&xn, g_xn);
    cudaGetSymbolAddress((void**)&qkvp, g_qkv);
    cudaGetSymbolAddress((void**)&attp, g_att);

    // 1) LayerNorm
    ln_kernel<<<NROWS, 256>>>(x, lng, lnb, xn);

    // 2) QKV projection: [8192,768] @ [768,2304]
    dim3 g1(QKVN / 64, NROWS / 128);
    sgemm_kernel<false><<<g1, 256>>>(xn, Wqkv, nullptr, qkvp, NROWS, QKVN, DIMSZ);

    // 3) Attention (flash-style) with relative position bias
    int smem = (3 * 64 * QP + 64 * VP) * (int)sizeof(float);
    cudaFuncSetAttribute(attn_kernel, cudaFuncAttributeMaxDynamicSharedMemorySize, smem);
    attn_kernel<<<dim3(NTOK / 64, HEADS, BATCH), 256, smem>>>(qkvp, rpb, attp);

    // 4) Output projection: [8192,768] @ [768,768] + bias
    dim3 g2(DIMSZ / 64, NROWS / 128);
    sgemm_kernel<true><<<g2, 256>>>(attp, Wout, bout, out, NROWS, DIMSZ, DIMSZ);
}

// round 4
// speedup vs baseline: 1.3604x; 1.3604x over previous
#include <cuda_runtime.h>
#include <cuda_bf16.h>
#include <cstdint>

#define DIMSZ 768
#define NTOK 1024
#define BATCH 8
#define HEADS 12
#define DH 64
#define NROWS (BATCH * NTOK)      /* 8192 */
#define QKVN (3 * DIMSZ)          /* 2304 */
#define SCALE 0.125f              /* DH^-0.5 */

#define QP 65
#define VP 68

// Scratch (device globals: allocation-free)
__device__ float g_xn[NROWS * DIMSZ];
__device__ float g_qkv[NROWS * QKVN];
__device__ float g_att[NROWS * DIMSZ];

// ===========================================================================
// helpers
// ===========================================================================
__device__ __forceinline__ uint32_t smem_u32(const void* p) {
    uint32_t a;
    asm("{ .reg .u64 t; cvta.to.shared.u64 t, %1; cvt.u32.u64 %0, t; }" : "=r"(a) : "l"(p));
    return a;
}

__device__ __forceinline__ void ldsm_x4(uint32_t addr, uint32_t* r) {
    asm volatile("ldmatrix.sync.aligned.m8n8.x4.shared.b16 {%0,%1,%2,%3}, [%4];"
                 : "=r"(r[0]), "=r"(r[1]), "=r"(r[2]), "=r"(r[3]) : "r"(addr));
}

__device__ __forceinline__ void mma16816(float* c, const uint32_t* a, uint32_t b0, uint32_t b1) {
    asm volatile("mma.sync.aligned.m16n8k16.row.col.f32.bf16.bf16.f32 "
                 "{%0,%1,%2,%3}, {%4,%5,%6,%7}, {%8,%9}, {%0,%1,%2,%3};"
                 : "+f"(c[0]), "+f"(c[1]), "+f"(c[2]), "+f"(c[3])
                 : "r"(a[0]), "r"(a[1]), "r"(a[2]), "r"(a[3]), "r"(b0), "r"(b1));
}

__device__ __forceinline__ void split_bf16(float x, unsigned short& h, unsigned short& l) {
    __nv_bfloat16 hb = __float2bfloat16_rn(x);
    float hf = __bfloat162float(hb);
    __nv_bfloat16 lb = __float2bfloat16_rn(x - hf);
    h = __bfloat16_as_ushort(hb);
    l = __bfloat16_as_ushort(lb);
}

// ===========================================================================
// Split-bf16 GEMM via mma.sync: C[M,N] = A[M,768] @ B[768,N] (+bias)
// CTA 128x128, 8 warps (64x32 each), KC=32 double-buffered.
// SMEM tiles (hi/lo A, hi/lo B): 128 rows x 80 bytes (32 bf16 + 16B pad;
// stride 80 keeps every ldmatrix row address 16B-aligned and the 8-row
// phase pattern conflict-free: r*80 mod 128 = {0,80,32,112,64,16,96,48}).
// ===========================================================================
#define TROW 80
#define TILE (128 * TROW)         /* 10240 */
#define STAGE (4 * TILE)          /* 40960 */
#define GEMM_SMEM (2 * STAGE)     /* 81920 */
#define KC 32
#define NSTAGE (DIMSZ / KC)       /* 24 */

template <bool HAS_BIAS>
__global__ __launch_bounds__(256, 1) void mma_gemm(const float* __restrict__ A,
                                                   const float* __restrict__ B,
                                                   const float* __restrict__ bias,
                                                   float* __restrict__ C,
                                                   int Nsz) {
    extern __shared__ char smem[];
    const uint32_t smb = smem_u32(smem);
    const int t = threadIdx.x;
    const int wid = t >> 5, lane = t & 31;
    const int m0 = blockIdx.y * 128, n0 = blockIdx.x * 128;
    const int wm = (wid >> 2) * 64, wn = (wid & 3) * 32;

    float acc[4][4][4];
#pragma unroll
    for (int i = 0; i < 4; i++)
#pragma unroll
        for (int j = 0; j < 4; j++)
#pragma unroll
            for (int k = 0; k < 4; k++) acc[i][j][k] = 0.f;

    // fill-side indexing
    const int arow = t >> 1;             // 0..127
    const int acol = (t & 1) * 16;       // fp32 col offset (0 or 16)
    const int bk0 = (t >> 5) * 4;        // k offset 0..28
    const int bl = t & 31;               // n lane

    float areg[16], breg[16];

    // ---- gmem loads into registers ----
    auto loadA = [&](int c) {
#pragma unroll
        for (int i = 0; i < 4; i++) {
            float4 v = *(const float4*)&A[(size_t)(m0 + arow) * DIMSZ + c * KC + acol + i * 4];
            areg[i * 4 + 0] = v.x; areg[i * 4 + 1] = v.y;
            areg[i * 4 + 2] = v.z; areg[i * 4 + 3] = v.w;
        }
    };
    auto loadB = [&](int c) {
#pragma unroll
        for (int j = 0; j < 4; j++) {
            const float* bp = &B[(size_t)(c * KC + bk0) * Nsz + n0 + bl + j * 32];
#pragma unroll
            for (int i = 0; i < 4; i++) breg[j * 4 + i] = bp[(size_t)i * Nsz];
        }
    };

    // ---- convert + smem stores ----
    auto storeA = [&](int st) {
        char* sAh = smem + st * STAGE;
        char* sAl = sAh + TILE;
        uint32_t off = (uint32_t)(arow * TROW + acol * 2);
#pragma unroll
        for (int j = 0; j < 4; j++) {
            unsigned short h[4], l[4];
#pragma unroll
            for (int i = 0; i < 4; i++) split_bf16(areg[j * 4 + i], h[i], l[i]);
            uint2 hp, lp;
            hp.x = (uint32_t)h[0] | ((uint32_t)h[1] << 16);
            hp.y = (uint32_t)h[2] | ((uint32_t)h[3] << 16);
            lp.x = (uint32_t)l[0] | ((uint32_t)l[1] << 16);
            lp.y = (uint32_t)l[2] | ((uint32_t)l[3] << 16);
            *(uint2*)(sAh + off + j * 8) = hp;
            *(uint2*)(sAl + off + j * 8) = lp;
        }
    };
    auto storeB = [&](int st) {
        char* sBh = smem + st * STAGE + 2 * TILE;
        char* sBl = sBh + TILE;
#pragma unroll
        for (int j = 0; j < 4; j++) {
            int n = bl + j * 32;
            unsigned short h[4], l[4];
#pragma unroll
            for (int i = 0; i < 4; i++) split_bf16(breg[j * 4 + i], h[i], l[i]);
            uint2 hp, lp;
            hp.x = (uint32_t)h[0] | ((uint32_t)h[1] << 16);
            hp.y = (uint32_t)h[2] | ((uint32_t)h[3] << 16);
            lp.x = (uint32_t)l[0] | ((uint32_t)l[1] << 16);
            lp.y = (uint32_t)l[2] | ((uint32_t)l[3] << 16);
            uint32_t off = (uint32_t)(n * TROW + bk0 * 2);
            *(uint2*)(sBh + off) = hp;
            *(uint2*)(sBl + off) = lp;
        }
    };

    // ---- MMA compute on one stage (two k16 steps) ----
    auto compute = [&](int st) {
        const uint32_t base = smb + st * STAGE;
#pragma unroll
        for (int ks = 0; ks < 2; ks++) {
            uint32_t Ah[4][4], Al[4][4], Bh[2][4], Bl[2][4];
            const uint32_t akb = (uint32_t)(ks * 32 + ((lane & 16) ? 16 : 0));
#pragma unroll
            for (int mt = 0; mt < 4; mt++) {
                uint32_t ra = base + (uint32_t)((wm + mt * 16 + (lane & 15)) * TROW) + akb;
                ldsm_x4(ra, Ah[mt]);
                ldsm_x4(ra + TILE, Al[mt]);
            }
            const uint32_t bkb = (uint32_t)(ks * 32 + ((lane & 8) ? 16 : 0));
            const int brow = ((lane >> 4) << 3) + (lane & 7);
#pragma unroll
            for (int bt = 0; bt < 2; bt++) {
                uint32_t rb = base + 2 * TILE + (uint32_t)((wn + bt * 16 + brow) * TROW) + bkb;
                ldsm_x4(rb, Bh[bt]);
                ldsm_x4(rb + TILE, Bl[bt]);
            }
#pragma unroll
            for (int mt = 0; mt < 4; mt++) {
#pragma unroll
                for (int nt = 0; nt < 4; nt++) {
                    uint32_t b0h = Bh[nt >> 1][(nt & 1) * 2], b1h = Bh[nt >> 1][(nt & 1) * 2 + 1];
                    uint32_t b0l = Bl[nt >> 1][(nt & 1) * 2], b1l = Bl[nt >> 1][(nt & 1) * 2 + 1];
                    mma16816(acc[mt][nt], Ah[mt], b0h, b1h);
                    mma16816(acc[mt][nt], Ah[mt], b0l, b1l);
                    mma16816(acc[mt][nt], Al[mt], b0h, b1h);
                }
            }
        }
    };

    // ---- pipeline ----
    loadA(0); loadB(0);
    storeA(0); storeB(0);
    __syncthreads();
    for (int c = 0; c < NSTAGE; c++) {
        const int st = c & 1;
        if (c + 1 < NSTAGE) { loadA(c + 1); loadB(c + 1); }
        compute(st);
        if (c + 1 < NSTAGE) { storeA(st ^ 1); storeB(st ^ 1); }
        __syncthreads();
    }

    // ---- epilogue ----
#pragma unroll
    for (int mt = 0; mt < 4; mt++) {
        int m = m0 + wm + mt * 16 + (lane >> 2);
#pragma unroll
        for (int nt = 0; nt < 4; nt++) {
            int n = n0 + wn + nt * 8 + (lane & 3) * 2;
            float bx = 0.f, by = 0.f;
            if (HAS_BIAS) { bx = bias[n]; by = bias[n + 1]; }
            float2 v0 = make_float2(acc[mt][nt][0] + bx, acc[mt][nt][1] + by);
            float2 v1 = make_float2(acc[mt][nt][2] + bx, acc[mt][nt][3] + by);
            *(float2*)&C[(size_t)m * Nsz + n] = v0;
            *(float2*)&C[(size_t)(m + 8) * Nsz + n] = v1;
        }
    }
}

// ---------------------------------------------------------------------------
// LayerNorm: one block per row of 768
// ---------------------------------------------------------------------------
__global__ __launch_bounds__(256) void ln_kernel(const float* __restrict__ x,
                                                 const float* __restrict__ gamma,
                                                 const float* __restrict__ beta,
                                                 float* __restrict__ y) {
    int row = blockIdx.x;
    int t = threadIdx.x;
    const float* xr = x + (size_t)row * DIMSZ;
    float v0 = xr[t], v1 = xr[t + 256], v2 = xr[t + 512];
    float s = v0 + v1 + v2;
    float ss = v0 * v0 + v1 * v1 + v2 * v2;
#pragma unroll
    for (int o = 16; o > 0; o >>= 1) {
        s += __shfl_xor_sync(0xffffffffu, s, o);
        ss += __shfl_xor_sync(0xffffffffu, ss, o);
    }
    __shared__ float sb[8], ssb[8];
    __shared__ float smu, srstd;
    if ((t & 31) == 0) { sb[t >> 5] = s; ssb[t >> 5] = ss; }
    __syncthreads();
    if (t == 0) {
        float S = 0.f, SS = 0.f;
#pragma unroll
        for (int i = 0; i < 8; i++) { S += sb[i]; SS += ssb[i]; }
        float mu = S * (1.0f / DIMSZ);
        float var = SS * (1.0f / DIMSZ) - mu * mu;
        smu = mu;
        srstd = rsqrtf(var + 1e-5f);
    }
    __syncthreads();
    float mu = smu, rstd = srstd;
    float* yr = y + (size_t)row * DIMSZ;
    yr[t]       = (v0 - mu) * rstd * gamma[t]       + beta[t];
    yr[t + 256] = (v1 - mu) * rstd * gamma[t + 256] + beta[t + 256];
    yr[t + 512] = (v2 - mu) * rstd * gamma[t + 512] + beta[t + 512];
}

// ---------------------------------------------------------------------------
// Flash-style attention with relative position bias (SIMT)
// ---------------------------------------------------------------------------
__global__ __launch_bounds__(256) void attn_kernel(const float* __restrict__ qkv,
                                                   const float* __restrict__ rpb,
                                                   float* __restrict__ out) {
    extern __shared__ float sm[];
    float* Qs = sm;
    float* Ks = Qs + 64 * QP;
    float* Ps = Ks + 64 * QP;
    float* Vs = Ps + 64 * QP;

    int t = threadIdx.x;
    int tx = t & 15, ty = t >> 4;
    int b = blockIdx.z, h = blockIdx.y;
    int i0 = blockIdx.x * 64;

    const float* qbase = qkv + (size_t)b * NTOK * QKVN + h * DH;
    const float* kbase = qbase + DIMSZ;
    const float* vbase = qbase + 2 * DIMSZ;
    const float* biasb = rpb + ((size_t)h * NTOK + i0) * NTOK;

#pragma unroll
    for (int i = 0; i < 4; i++) {
        int f = t + i * 256;
        int row = f >> 4, c4 = f & 15;
        float4 v = *(const float4*)&qbase[(size_t)(i0 + row) * QKVN + c4 * 4];
        float* dst = &Qs[row * QP + c4 * 4];
        dst[0] = v.x; dst[1] = v.y; dst[2] = v.z; dst[3] = v.w;
    }

    float acc[4][4];
    float mrow[4], lrow[4];
#pragma unroll
    for (int r = 0; r < 4; r++) {
        mrow[r] = -1e30f;
        lrow[r] = 0.f;
#pragma unroll
        for (int c = 0; c < 4; c++) acc[r][c] = 0.f;
    }

    const int qrow = ty * 4 * QP;
    const int krow = tx * 4 * QP;

    for (int j0 = 0; j0 < NTOK; j0 += 64) {
        __syncthreads();
#pragma unroll
        for (int i = 0; i < 4; i++) {
            int f = t + i * 256;
            int row = f >> 4, c4 = f & 15;
            float4 kv = *(const float4*)&kbase[(size_t)(j0 + row) * QKVN + c4 * 4];
            float* kd = &Ks[row * QP + c4 * 4];
            kd[0] = kv.x; kd[1] = kv.y; kd[2] = kv.z; kd[3] = kv.w;
            float4 vv = *(const float4*)&vbase[(size_t)(j0 + row) * QKVN + c4 * 4];
            *(float4*)&Vs[row * VP + c4 * 4] = vv;
        }
        __syncthreads();

        float s[4][4];
#pragma unroll
        for (int r = 0; r < 4; r++)
#pragma unroll
            for (int c = 0; c < 4; c++) s[r][c] = 0.f;
#pragma unroll 16
        for (int d = 0; d < DH; d++) {
            float a0 = Qs[qrow + d];
            float a1 = Qs[qrow + QP + d];
            float a2 = Qs[qrow + 2 * QP + d];
            float a3 = Qs[qrow + 3 * QP + d];
            float b0 = Ks[krow + d];
            float b1 = Ks[krow + QP + d];
            float b2 = Ks[krow + 2 * QP + d];
            float b3 = Ks[krow + 3 * QP + d];
            s[0][0] += a0 * b0; s[0][1] += a0 * b1; s[0][2] += a0 * b2; s[0][3] += a0 * b3;
            s[1][0] += a1 * b0; s[1][1] += a1 * b1; s[1][2] += a1 * b2; s[1][3] += a1 * b3;
            s[2][0] += a2 * b0; s[2][1] += a2 * b1; s[2][2] += a2 * b2; s[2][3] += a2 * b3;
            s[3][0] += a3 * b0; s[3][1] += a3 * b1; s[3][2] += a3 * b2; s[3][3] += a3 * b3;
        }

#pragma unroll
        for (int r = 0; r < 4; r++) {
            float4 b4 = *(const float4*)&biasb[(size_t)(ty * 4 + r) * NTOK + j0 + tx * 4];
            s[r][0] = s[r][0] * SCALE + b4.x;
            s[r][1] = s[r][1] * SCALE + b4.y;
            s[r][2] = s[r][2] * SCALE + b4.z;
            s[r][3] = s[r][3] * SCALE + b4.w;

            float tmax = fmaxf(fmaxf(s[r][0], s[r][1]), fmaxf(s[r][2], s[r][3]));
#pragma unroll
            for (int o = 8; o > 0; o >>= 1)
                tmax = fmaxf(tmax, __shfl_xor_sync(0xffffffffu, tmax, o));
            float newm = fmaxf(mrow[r], tmax);
            float p0 = __expf(s[r][0] - newm);
            float p1 = __expf(s[r][1] - newm);
            float p2 = __expf(s[r][2] - newm);
            float p3 = __expf(s[r][3] - newm);
            float tsum = p0 + p1 + p2 + p3;
#pragma unroll
            for (int o = 8; o > 0; o >>= 1)
                tsum += __shfl_xor_sync(0xffffffffu, tsum, o);
            float factor = __expf(mrow[r] - newm);
            lrow[r] = lrow[r] * factor + tsum;
            mrow[r] = newm;
            acc[r][0] *= factor; acc[r][1] *= factor;
            acc[r][2] *= factor; acc[r][3] *= factor;
            float* pd = &Ps[(ty * 4 + r) * QP + tx * 4];
            pd[0] = p0; pd[1] = p1; pd[2] = p2; pd[3] = p3;
        }
        __syncthreads();

#pragma unroll 16
        for (int j = 0; j < 64; j++) {
            float4 vv = *(const float4*)&Vs[j * VP + tx * 4];
            float p0 = Ps[qrow + j];
            float p1 = Ps[qrow + QP + j];
            float p2 = Ps[qrow + 2 * QP + j];
            float p3 = Ps[qrow + 3 * QP + j];
            acc[0][0] += p0 * vv.x; acc[0][1] += p0 * vv.y; acc[0][2] += p0 * vv.z; acc[0][3] += p0 * vv.w;
            acc[1][0] += p1 * vv.x; acc[1][1] += p1 * vv.y; acc[1][2] += p1 * vv.z; acc[1][3] += p1 * vv.w;
            acc[2][0] += p2 * vv.x; acc[2][1] += p2 * vv.y; acc[2][2] += p2 * vv.z; acc[2][3] += p2 * vv.w;
            acc[3][0] += p3 * vv.x; acc[3][1] += p3 * vv.y; acc[3][2] += p3 * vv.z; acc[3][3] += p3 * vv.w;
        }
    }

    float* ob = out + ((size_t)(b * NTOK + i0)) * DIMSZ + h * DH;
#pragma unroll
    for (int r = 0; r < 4; r++) {
        float inv = 1.0f / lrow[r];
        float4 o = make_float4(acc[r][0] * inv, acc[r][1] * inv,
                               acc[r][2] * inv, acc[r][3] * inv);
        *(float4*)&ob[(size_t)(ty * 4 + r) * DIMSZ + tx * 4] = o;
    }
}

// ---------------------------------------------------------------------------
extern "C" void kernel_launch(void* const* d_in, const int* in_sizes, int n_in,
                              void* d_out, int out_size) {
    const float* x    = (const float*)d_in[0];
    const float* rpb  = (const float*)d_in[1];
    const float* Wqkv = (const float*)d_in[2];
    const float* Wout = (const float*)d_in[3];
    const float* bout = (const float*)d_in[4];
    const float* lng  = (const float*)d_in[5];
    const float* lnb  = (const float*)d_in[6];
    float* out = (float*)d_out;

    float *xn, *qkvp, *attp;
    cudaGetSymbolAddress((void**)&xn, g_xn);
    cudaGetSymbolAddress((void**)&qkvp, g_qkv);
    cudaGetSymbolAddress((void**)&attp, g_att);

    // 1) LayerNorm
    ln_kernel<<<NROWS, 256>>>(x, lng, lnb, xn);

    // 2) QKV projection: [8192,768] @ [768,2304]  (mma.sync split-bf16)
    cudaFuncSetAttribute(mma_gemm<false>, cudaFuncAttributeMaxDynamicSharedMemorySize, GEMM_SMEM);
    mma_gemm<false><<<dim3(QKVN / 128, NROWS / 128), 256, GEMM_SMEM>>>(xn, Wqkv, nullptr, qkvp, QKVN);

    // 3) Attention (flash-style) with relative position bias
    int smem = (3 * 64 * QP + 64 * VP) * (int)sizeof(float);
    cudaFuncSetAttribute(attn_kernel, cudaFuncAttributeMaxDynamicSharedMemorySize, smem);
    attn_kernel<<<dim3(NTOK / 64, HEADS, BATCH), 256, smem>>>(qkvp, rpb, attp);

    // 4) Output projection: [8192,768] @ [768,768] + bias  (mma.sync split-bf16)
    cudaFuncSetAttribute(mma_gemm<true>, cudaFuncAttributeMaxDynamicSharedMemorySize, GEMM_SMEM);
    mma_gemm<true><<<dim3(DIMSZ / 128, NROWS / 128), 256, GEMM_SMEM>>>(attp, Wout, bout, out, DIMSZ);
}

// round 5
// speedup vs baseline: 1.9523x; 1.4351x over previous
#include <cuda_runtime.h>
#include <cuda_bf16.h>
#include <cstdint>

#define DIMSZ 768
#define NTOK 1024
#define BATCH 8
#define HEADS 12
#define DH 64
#define NROWS (BATCH * NTOK)      /* 8192 */
#define QKVN (3 * DIMSZ)          /* 2304 */
#define SCALE 0.125f              /* DH^-0.5 */

typedef unsigned short u16;
typedef uint32_t u32;

// ---------------- scratch (device globals, allocation-free) ----------------
__device__ u16 g_xnh[NROWS * DIMSZ];
__device__ u16 g_xnl[NROWS * DIMSZ];
__device__ u16 g_wqh[QKVN * DIMSZ];      // Wqkv^T hi  [2304][768]
__device__ u16 g_wql[QKVN * DIMSZ];
__device__ u16 g_woh[DIMSZ * DIMSZ];     // Wout^T hi  [768][768]
__device__ u16 g_wol[DIMSZ * DIMSZ];
__device__ u16 g_qkvh[NROWS * QKVN];
__device__ u16 g_qkvl[NROWS * QKVN];
__device__ u16 g_vth[BATCH * HEADS * DH * NTOK];   // V^T [b][h][d][j]
__device__ u16 g_vtl[BATCH * HEADS * DH * NTOK];
__device__ u16 g_atth[NROWS * DIMSZ];
__device__ u16 g_attl[NROWS * DIMSZ];

// ---------------- helpers ----------------
__device__ __forceinline__ u32 smem_u32(const void* p) {
    u32 a;
    asm("{ .reg .u64 t; cvta.to.shared.u64 t, %1; cvt.u32.u64 %0, t; }" : "=r"(a) : "l"(p));
    return a;
}
__device__ __forceinline__ void ldsm_x4(u32 addr, u32* r) {
    asm volatile("ldmatrix.sync.aligned.m8n8.x4.shared.b16 {%0,%1,%2,%3}, [%4];"
                 : "=r"(r[0]), "=r"(r[1]), "=r"(r[2]), "=r"(r[3]) : "r"(addr));
}
__device__ __forceinline__ void mma16816(float* c, const u32* a, u32 b0, u32 b1) {
    asm volatile("mma.sync.aligned.m16n8k16.row.col.f32.bf16.bf16.f32 "
                 "{%0,%1,%2,%3}, {%4,%5,%6,%7}, {%8,%9}, {%0,%1,%2,%3};"
                 : "+f"(c[0]), "+f"(c[1]), "+f"(c[2]), "+f"(c[3])
                 : "r"(a[0]), "r"(a[1]), "r"(a[2]), "r"(a[3]), "r"(b0), "r"(b1));
}
#define CP16(dst, src) \
    asm volatile("cp.async.cg.shared.global [%0], [%1], 16;" :: "r"(dst), "l"(src))
#define CP_COMMIT() asm volatile("cp.async.commit_group;" ::: "memory")
#define CP_WAIT0()  asm volatile("cp.async.wait_group 0;" ::: "memory")
#define CP_WAIT1()  asm volatile("cp.async.wait_group 1;" ::: "memory")
#define CP_WAIT2()  asm volatile("cp.async.wait_group 2;" ::: "memory")

__device__ __forceinline__ void split_bf16(float x, u16& h, u16& l) {
    __nv_bfloat16 hb = __float2bfloat16_rn(x);
    float hf = __bfloat162float(hb);
    __nv_bfloat16 lb = __float2bfloat16_rn(x - hf);
    h = __bfloat16_as_ushort(hb);
    l = __bfloat16_as_ushort(lb);
}
// split two floats -> (hiPacked, loPacked); a in low half, b in high half
__device__ __forceinline__ void split2(float a, float b, u32& hp, u32& lp) {
    u16 ha, la, hb, lb;
    split_bf16(a, ha, la);
    split_bf16(b, hb, lb);
    hp = (u32)ha | ((u32)hb << 16);
    lp = (u32)la | ((u32)lb << 16);
}

// ===========================================================================
// LayerNorm -> split bf16 hi/lo
// ===========================================================================
__global__ __launch_bounds__(256) void ln_kernel(const float* __restrict__ x,
                                                 const float* __restrict__ gamma,
                                                 const float* __restrict__ beta,
                                                 u16* __restrict__ yh,
                                                 u16* __restrict__ yl) {
    int row = blockIdx.x;
    int t = threadIdx.x;
    __shared__ float sv[DIMSZ];
    __shared__ float sb[8], ssb[8];
    __shared__ float smu, srstd;
    const float* xr = x + (size_t)row * DIMSZ;
    float v0 = xr[t], v1 = xr[t + 256], v2 = xr[t + 512];
    float s = v0 + v1 + v2;
    float ss = v0 * v0 + v1 * v1 + v2 * v2;
#pragma unroll
    for (int o = 16; o > 0; o >>= 1) {
        s += __shfl_xor_sync(0xffffffffu, s, o);
        ss += __shfl_xor_sync(0xffffffffu, ss, o);
    }
    if ((t & 31) == 0) { sb[t >> 5] = s; ssb[t >> 5] = ss; }
    __syncthreads();
    if (t == 0) {
        float S = 0.f, SS = 0.f;
#pragma unroll
        for (int i = 0; i < 8; i++) { S += sb[i]; SS += ssb[i]; }
        float mu = S * (1.0f / DIMSZ);
        float var = SS * (1.0f / DIMSZ) - mu * mu;
        smu = mu;
        srstd = rsqrtf(var + 1e-5f);
    }
    __syncthreads();
    float mu = smu, rstd = srstd;
    sv[t]       = (v0 - mu) * rstd * gamma[t]       + beta[t];
    sv[t + 256] = (v1 - mu) * rstd * gamma[t + 256] + beta[t + 256];
    sv[t + 512] = (v2 - mu) * rstd * gamma[t + 512] + beta[t + 512];
    __syncthreads();
    u32* oh = (u32*)(yh + (size_t)row * DIMSZ);
    u32* ol = (u32*)(yl + (size_t)row * DIMSZ);
    for (int p = t; p < DIMSZ / 2; p += 256) {
        u32 hp, lp;
        split2(sv[2 * p], sv[2 * p + 1], hp, lp);
        oh[p] = hp;
        ol[p] = lp;
    }
}

// ===========================================================================
// Weight transpose + split: W[768][N] -> Wt hi/lo [N][768]
// ===========================================================================
__global__ __launch_bounds__(256) void wprep_kernel(const float* __restrict__ W,
                                                    u16* __restrict__ Wth,
                                                    u16* __restrict__ Wtl,
                                                    int Nsz) {
    __shared__ float sm[32][33];
    int tx = threadIdx.x & 31, ty = threadIdx.x >> 5;   // 32 x 8
    int n0 = blockIdx.x * 32, k0 = blockIdx.y * 32;
#pragma unroll
    for (int i = 0; i < 4; i++)
        sm[ty + i * 8][tx] = W[(size_t)(k0 + ty + i * 8) * Nsz + n0 + tx];
    __syncthreads();
#pragma unroll
    for (int i = 0; i < 4; i++) {
        int n = n0 + ty + i * 8, k = k0 + tx;
        u16 h, l;
        split_bf16(sm[tx][ty + i * 8], h, l);
        Wth[(size_t)n * DIMSZ + k] = h;
        Wtl[(size_t)n * DIMSZ + k] = l;
    }
}

// ===========================================================================
// V transpose: qkv (V part) [b][j][h*64+d] -> vt [b][h][d][j]
// ===========================================================================
__global__ __launch_bounds__(256) void vtrans_kernel(const u16* __restrict__ qh,
                                                     const u16* __restrict__ ql,
                                                     u16* __restrict__ vh,
                                                     u16* __restrict__ vl) {
    __shared__ u16 sm[64][66];
    int t = threadIdx.x;
    int j0 = blockIdx.x * 64, h = blockIdx.y, b = blockIdx.z;
    const u16* srcs[2] = {qh, ql};
    u16* dsts[2] = {vh, vl};
#pragma unroll
    for (int pass = 0; pass < 2; pass++) {
        const u16* src = srcs[pass];
        u16* dst = dsts[pass];
#pragma unroll
        for (int i = 0; i < 8; i++) {
            int id = t + i * 256;          // 0..2047
            int jj = id >> 5, dp = id & 31;
            u32 v = *(const u32*)(src + (size_t)(b * NTOK + j0 + jj) * QKVN +
                                  2 * DIMSZ + h * DH + dp * 2);
            sm[jj][2 * dp] = (u16)v;
            sm[jj][2 * dp + 1] = (u16)(v >> 16);
        }
        __syncthreads();
#pragma unroll
        for (int i = 0; i < 8; i++) {
            int id = t + i * 256;
            int d = id >> 5, jp = id & 31;
            u32 v = (u32)sm[2 * jp][d] | ((u32)sm[2 * jp + 1][d] << 16);
            *(u32*)(dst + ((size_t)((b * HEADS + h) * DH + d)) * NTOK + j0 + 2 * jp) = v;
        }
        __syncthreads();
    }
}

// ===========================================================================
// Split-bf16 GEMM (cp.async 4-stage): C[M,N] = A[M,768] @ Bt[N,768]^T
// A,Bt pre-split bf16 hi/lo in gmem. CTA 128x128, 8 warps, KC=32.
// EPI 0: fp32 out + bias.  EPI 1: split bf16 out (hi/lo), SCALE on n<768.
// ===========================================================================
#define TROW 80
#define TILE (128 * TROW)         /* 10240 */
#define STAGE (4 * TILE)          /* 40960 */
#define NBUF 4
#define GEMM_SMEM (NBUF * STAGE)  /* 163840 */
#define KC 32
#define NSTAGE (DIMSZ / KC)       /* 24 */

template <int EPI>
__global__ __launch_bounds__(256, 1) void mma_gemm(const u16* __restrict__ Ah,
                                                   const u16* __restrict__ Al,
                                                   const u16* __restrict__ Bh,
                                                   const u16* __restrict__ Bl,
                                                   const float* __restrict__ bias,
                                                   float* __restrict__ Cf,
                                                   u16* __restrict__ Ch,
                                                   u16* __restrict__ Cl,
                                                   int Nsz) {
    extern __shared__ char smem[];
    const u32 smb = smem_u32(smem);
    const int t = threadIdx.x;
    const int wid = t >> 5, lane = t & 31;
    const int m0 = blockIdx.y * 128, n0 = blockIdx.x * 128;
    const int wm = (wid >> 2) * 64, wn = (wid & 3) * 32;

    float acc[4][4][4];
#pragma unroll
    for (int i = 0; i < 4; i++)
#pragma unroll
        for (int j = 0; j < 4; j++)
#pragma unroll
            for (int k = 0; k < 4; k++) acc[i][j][k] = 0.f;

    const int frow = t >> 1;          // 0..127
    const int half = t & 1;

    auto fill = [&](int c) {
        const int bf = c % NBUF;
        const u32 base = smb + bf * STAGE;
        const size_t aoff = (size_t)(m0 + frow) * DIMSZ + c * KC + half * 16;
        const size_t boff = (size_t)(n0 + frow) * DIMSZ + c * KC + half * 16;
        const u32 doff = (u32)(frow * TROW + half * 32);
#pragma unroll
        for (int i = 0; i < 2; i++) {
            CP16(base + doff + i * 16, Ah + aoff + i * 8);
            CP16(base + TILE + doff + i * 16, Al + aoff + i * 8);
            CP16(base + 2 * TILE + doff + i * 16, Bh + boff + i * 8);
            CP16(base + 3 * TILE + doff + i * 16, Bl + boff + i * 8);
        }
    };

    auto compute = [&](int c) {
        const u32 base = smb + (c % NBUF) * STAGE;
#pragma unroll
        for (int ks = 0; ks < 2; ks++) {
            u32 Ahf[4][4], Alf[4][4], Bhf[2][4], Blf[2][4];
            const u32 akb = (u32)(ks * 32 + ((lane & 16) ? 16 : 0));
#pragma unroll
            for (int mt = 0; mt < 4; mt++) {
                u32 ra = base + (u32)((wm + mt * 16 + (lane & 15)) * TROW) + akb;
                ldsm_x4(ra, Ahf[mt]);
                ldsm_x4(ra + TILE, Alf[mt]);
            }
            const u32 bkb = (u32)(ks * 32 + ((lane & 8) ? 16 : 0));
            const int brow = ((lane >> 4) << 3) + (lane & 7);
#pragma unroll
            for (int bt = 0; bt < 2; bt++) {
                u32 rb = base + 2 * TILE + (u32)((wn + bt * 16 + brow) * TROW) + bkb;
                ldsm_x4(rb, Bhf[bt]);
                ldsm_x4(rb + TILE, Blf[bt]);
            }
#pragma unroll
            for (int mt = 0; mt < 4; mt++) {
#pragma unroll
                for (int nt = 0; nt < 4; nt++) {
                    u32 b0h = Bhf[nt >> 1][(nt & 1) * 2], b1h = Bhf[nt >> 1][(nt & 1) * 2 + 1];
                    u32 b0l = Blf[nt >> 1][(nt & 1) * 2], b1l = Blf[nt >> 1][(nt & 1) * 2 + 1];
                    mma16816(acc[mt][nt], Ahf[mt], b0h, b1h);
                    mma16816(acc[mt][nt], Ahf[mt], b0l, b1l);
                    mma16816(acc[mt][nt], Alf[mt], b0h, b1h);
                }
            }
        }
    };

    // pipeline: fill 0..2, then steady state
    fill(0); CP_COMMIT();
    fill(1); CP_COMMIT();
    fill(2); CP_COMMIT();
    for (int c = 0; c < NSTAGE; c++) {
        CP_WAIT2();
        __syncthreads();
        if (c + 3 < NSTAGE) fill(c + 3);
        CP_COMMIT();
        compute(c);
    }

    // epilogue
#pragma unroll
    for (int mt = 0; mt < 4; mt++) {
        int m = m0 + wm + mt * 16 + (lane >> 2);
#pragma unroll
        for (int nt = 0; nt < 4; nt++) {
            int n = n0 + wn + nt * 8 + (lane & 3) * 2;
            if (EPI == 0) {
                float bx = bias[n], by = bias[n + 1];
                *(float2*)&Cf[(size_t)m * Nsz + n] =
                    make_float2(acc[mt][nt][0] + bx, acc[mt][nt][1] + by);
                *(float2*)&Cf[(size_t)(m + 8) * Nsz + n] =
                    make_float2(acc[mt][nt][2] + bx, acc[mt][nt][3] + by);
            } else {
                float sc = (n < DIMSZ) ? SCALE : 1.0f;   // fold softmax scale into Q
                u32 hp, lp;
                split2(acc[mt][nt][0] * sc, acc[mt][nt][1] * sc, hp, lp);
                *(u32*)(Ch + (size_t)m * Nsz + n) = hp;
                *(u32*)(Cl + (size_t)m * Nsz + n) = lp;
                split2(acc[mt][nt][2] * sc, acc[mt][nt][3] * sc, hp, lp);
                *(u32*)(Ch + (size_t)(m + 8) * Nsz + n) = hp;
                *(u32*)(Cl + (size_t)(m + 8) * Nsz + n) = lp;
            }
        }
    }
}

// ===========================================================================
// Attention via mma.sync, 3-term split-bf16 for QK^T and PV.
// Block = 128 thr (4 warps), one (b,h,64-q-row tile). K/V cp.async double-buf.
// ===========================================================================
#define AROW 144
#define ATILE (64 * AROW)          /* 9216 */
#define AKV (4 * ATILE)            /* one K/V buffer: Kh,Kl,Vh,Vl = 36864 */
#define ASMEM (2 * ATILE + 2 * AKV) /* Qh,Ql + 2 bufs = 92160 */

__global__ __launch_bounds__(128, 2) void attn_mma(const u16* __restrict__ qh,
                                                   const u16* __restrict__ ql,
                                                   const u16* __restrict__ vth,
                                                   const u16* __restrict__ vtl,
                                                   const float* __restrict__ rpb,
                                                   u16* __restrict__ oh,
                                                   u16* __restrict__ ol) {
    extern __shared__ char smem[];
    const u32 smb = smem_u32(smem);
    const int t = threadIdx.x;
    const int w = t >> 5, lane = t & 31;
    const int i0 = blockIdx.x * 64, h = blockIdx.y, b = blockIdx.z;

    const int frow = t >> 1, half = t & 1;
    const int brow = ((lane >> 4) << 3) + (lane & 7);

    // ---- Q tile -> smem (cp.async) ----
    {
        const size_t qoff = (size_t)(b * NTOK + i0 + frow) * QKVN + h * DH + half * 32;
        const u32 doff = (u32)(frow * AROW + half * 64);
#pragma unroll
        for (int i = 0; i < 4; i++) {
            CP16(smb + doff + i * 16, qh + qoff + i * 8);
            CP16(smb + ATILE + doff + i * 16, ql + qoff + i * 8);
        }
        CP_COMMIT();
    }

    auto fillKV = [&](int jt) {
        const u32 base = smb + 2 * ATILE + (jt & 1) * AKV;
        const size_t koff = (size_t)(b * NTOK + jt * 64 + frow) * QKVN + DIMSZ + h * DH + half * 32;
        const size_t voff = (size_t)((b * HEADS + h) * DH + frow) * NTOK + jt * 64 + half * 32;
        const u32 doff = (u32)(frow * AROW + half * 64);
#pragma unroll
        for (int i = 0; i < 4; i++) {
            CP16(base + doff + i * 16, qh + koff + i * 8);
            CP16(base + ATILE + doff + i * 16, ql + koff + i * 8);
            CP16(base + 2 * ATILE + doff + i * 16, vth + voff + i * 8);
            CP16(base + 3 * ATILE + doff + i * 16, vtl + voff + i * 8);
        }
    };

    fillKV(0); CP_COMMIT();

    // Q fragments (wait until Q group done; KV0 may still be in flight)
    CP_WAIT1();
    __syncthreads();
    u32 Aqh[4][4], Aql[4][4];
#pragma unroll
    for (int ks = 0; ks < 4; ks++) {
        u32 ra = smb + (u32)((w * 16 + (lane & 15)) * AROW) + ks * 32 + ((lane & 16) ? 16 : 0);
        ldsm_x4(ra, Aqh[ks]);
        ldsm_x4(ra + ATILE, Aql[ks]);
    }

    // online softmax state (rows rA = lane>>2, rB = rA+8 within warp's m16)
    float o[8][4];
#pragma unroll
    for (int nt = 0; nt < 8; nt++)
#pragma unroll
        for (int k = 0; k < 4; k++) o[nt][k] = 0.f;
    float mA = -1e30f, mB = -1e30f, lA = 0.f, lB = 0.f;

    const float* bp = rpb + ((size_t)(h * NTOK + i0 + w * 16 + (lane >> 2))) * NTOK + 2 * (lane & 3);

    for (int jt = 0; jt < 16; jt++) {
        CP_WAIT0();
        __syncthreads();
        if (jt + 1 < 16) { fillKV(jt + 1); CP_COMMIT(); }

        const u32 kb = smb + 2 * ATILE + (jt & 1) * AKV;
        const u32 vb = kb + 2 * ATILE;

        // ---- S = Q K^T (3-term split) ----
        float s[8][4];
#pragma unroll
        for (int nt = 0; nt < 8; nt++)
#pragma unroll
            for (int k = 0; k < 4; k++) s[nt][k] = 0.f;
#pragma unroll
        for (int ks = 0; ks < 4; ks++) {
            u32 Bh[4][4], Bl[4][4];
            const u32 bkb = (u32)(ks * 32 + ((lane & 8) ? 16 : 0));
#pragma unroll
            for (int bt = 0; bt < 4; bt++) {
                u32 rb = kb + (u32)((bt * 16 + brow) * AROW) + bkb;
                ldsm_x4(rb, Bh[bt]);
                ldsm_x4(rb + ATILE, Bl[bt]);
            }
#pragma unroll
            for (int nt = 0; nt < 8; nt++) {
                u32 b0h = Bh[nt >> 1][(nt & 1) * 2], b1h = Bh[nt >> 1][(nt & 1) * 2 + 1];
                u32 b0l = Bl[nt >> 1][(nt & 1) * 2], b1l = Bl[nt >> 1][(nt & 1) * 2 + 1];
                mma16816(s[nt], Aqh[ks], b0h, b1h);
                mma16816(s[nt], Aqh[ks], b0l, b1l);
                mma16816(s[nt], Aql[ks], b0h, b1h);
            }
        }

        // ---- + bias, online softmax ----
        const float* bpj = bp + jt * 64;
        float tmA = -1e30f, tmB = -1e30f;
#pragma unroll
        for (int nt = 0; nt < 8; nt++) {
            float2 ba = *(const float2*)(bpj + nt * 8);
            float2 bb = *(const float2*)(bpj + 8 * NTOK + nt * 8);
            s[nt][0] += ba.x; s[nt][1] += ba.y;
            s[nt][2] += bb.x; s[nt][3] += bb.y;
            tmA = fmaxf(tmA, fmaxf(s[nt][0], s[nt][1]));
            tmB = fmaxf(tmB, fmaxf(s[nt][2], s[nt][3]));
        }
        tmA = fmaxf(tmA, __shfl_xor_sync(0xffffffffu, tmA, 1));
        tmA = fmaxf(tmA, __shfl_xor_sync(0xffffffffu, tmA, 2));
        tmB = fmaxf(tmB, __shfl_xor_sync(0xffffffffu, tmB, 1));
        tmB = fmaxf(tmB, __shfl_xor_sync(0xffffffffu, tmB, 2));
        float nmA = fmaxf(mA, tmA), nmB = fmaxf(mB, tmB);
        float facA = __expf(mA - nmA), facB = __expf(mB - nmB);
        mA = nmA; mB = nmB;
        float suA = 0.f, suB = 0.f;
#pragma unroll
        for (int nt = 0; nt < 8; nt++) {
            s[nt][0] = __expf(s[nt][0] - mA);
            s[nt][1] = __expf(s[nt][1] - mA);
            s[nt][2] = __expf(s[nt][2] - mB);
            s[nt][3] = __expf(s[nt][3] - mB);
            suA += s[nt][0] + s[nt][1];
            suB += s[nt][2] + s[nt][3];
            o[nt][0] *= facA; o[nt][1] *= facA;
            o[nt][2] *= facB; o[nt][3] *= facB;
        }
        suA += __shfl_xor_sync(0xffffffffu, suA, 1);
        suA += __shfl_xor_sync(0xffffffffu, suA, 2);
        suB += __shfl_xor_sync(0xffffffffu, suB, 1);
        suB += __shfl_xor_sync(0xffffffffu, suB, 2);
        lA = lA * facA + suA;
        lB = lB * facB + suB;

        // ---- P fragments (accumulator layout -> A layout), split hi/lo ----
        u32 Aph[4][4], Apl[4][4];
#pragma unroll
        for (int kt = 0; kt < 4; kt++) {
            split2(s[2 * kt][0], s[2 * kt][1], Aph[kt][0], Apl[kt][0]);
            split2(s[2 * kt][2], s[2 * kt][3], Aph[kt][1], Apl[kt][1]);
            split2(s[2 * kt + 1][0], s[2 * kt + 1][1], Aph[kt][2], Apl[kt][2]);
            split2(s[2 * kt + 1][2], s[2 * kt + 1][3], Aph[kt][3], Apl[kt][3]);
        }

        // ---- O += P V (3-term split), V^T in smem [d][j] ----
#pragma unroll
        for (int kt = 0; kt < 4; kt++) {
            u32 Bh[4][4], Bl[4][4];
            const u32 bkb = (u32)(kt * 32 + ((lane & 8) ? 16 : 0));
#pragma unroll
            for (int bt = 0; bt < 4; bt++) {
                u32 rb = vb + (u32)((bt * 16 + brow) * AROW) + bkb;
                ldsm_x4(rb, Bh[bt]);
                ldsm_x4(rb + ATILE, Bl[bt]);
            }
#pragma unroll
            for (int nt = 0; nt < 8; nt++) {
                u32 b0h = Bh[nt >> 1][(nt & 1) * 2], b1h = Bh[nt >> 1][(nt & 1) * 2 + 1];
                u32 b0l = Bl[nt >> 1][(nt & 1) * 2], b1l = Bl[nt >> 1][(nt & 1) * 2 + 1];
                mma16816(o[nt], Aph[kt], b0h, b1h);
                mma16816(o[nt], Aph[kt], b0l, b1l);
                mma16816(o[nt], Apl[kt], b0h, b1h);
            }
        }
    }

    // ---- epilogue: normalize, split, store ----
    float invA = 1.0f / lA, invB = 1.0f / lB;
    int rowA = b * NTOK + i0 + w * 16 + (lane >> 2);
#pragma unroll
    for (int nt = 0; nt < 8; nt++) {
        int col = h * DH + nt * 8 + 2 * (lane & 3);
        u32 hp, lp;
        split2(o[nt][0] * invA, o[nt][1] * invA, hp, lp);
        *(u32*)(oh + (size_t)rowA * DIMSZ + col) = hp;
        *(u32*)(ol + (size_t)rowA * DIMSZ + col) = lp;
        split2(o[nt][2] * invB, o[nt][3] * invB, hp, lp);
        *(u32*)(oh + (size_t)(rowA + 8) * DIMSZ + col) = hp;
        *(u32*)(ol + (size_t)(rowA + 8) * DIMSZ + col) = lp;
    }
}

// ---------------------------------------------------------------------------
extern "C" void kernel_launch(void* const* d_in, const int* in_sizes, int n_in,
                              void* d_out, int out_size) {
    const float* x    = (const float*)d_in[0];
    const float* rpb  = (const float*)d_in[1];
    const float* Wqkv = (const float*)d_in[2];
    const float* Wout = (const float*)d_in[3];
    const float* bout = (const float*)d_in[4];
    const float* lng  = (const float*)d_in[5];
    const float* lnb  = (const float*)d_in[6];
    float* out = (float*)d_out;

    u16 *xnh, *xnl, *wqh, *wql, *woh, *wol, *qkh, *qkl, *vth, *vtl, *ath, *atl;
    cudaGetSymbolAddress((void**)&xnh, g_xnh);
    cudaGetSymbolAddress((void**)&xnl, g_xnl);
    cudaGetSymbolAddress((void**)&wqh, g_wqh);
    cudaGetSymbolAddress((void**)&wql, g_wql);
    cudaGetSymbolAddress((void**)&woh, g_woh);
    cudaGetSymbolAddress((void**)&wol, g_wol);
    cudaGetSymbolAddress((void**)&qkh, g_qkvh);
    cudaGetSymbolAddress((void**)&qkl, g_qkvl);
    cudaGetSymbolAddress((void**)&vth, g_vth);
    cudaGetSymbolAddress((void**)&vtl, g_vtl);
    cudaGetSymbolAddress((void**)&ath, g_atth);
    cudaGetSymbolAddress((void**)&atl, g_attl);

    // 1) LN -> split bf16
    ln_kernel<<<NROWS, 256>>>(x, lng, lnb, xnh, xnl);

    // 1b) weight prep (transpose + split)
    wprep_kernel<<<dim3(QKVN / 32, DIMSZ / 32), 256>>>(Wqkv, wqh, wql, QKVN);
    wprep_kernel<<<dim3(DIMSZ / 32, DIMSZ / 32), 256>>>(Wout, woh, wol, DIMSZ);

    // 2) QKV projection (split-bf16 out, Q pre-scaled)
    cudaFuncSetAttribute(mma_gemm<1>, cudaFuncAttributeMaxDynamicSharedMemorySize, GEMM_SMEM);
    mma_gemm<1><<<dim3(QKVN / 128, NROWS / 128), 256, GEMM_SMEM>>>(
        xnh, xnl, wqh, wql, nullptr, nullptr, qkh, qkl, QKVN);

    // 2b) V transpose
    vtrans_kernel<<<dim3(NTOK / 64, HEADS, BATCH), 256>>>(qkh, qkl, vth, vtl);

    // 3) attention (tensor-core, split-bf16)
    cudaFuncSetAttribute(attn_mma, cudaFuncAttributeMaxDynamicSharedMemorySize, ASMEM);
    attn_mma<<<dim3(NTOK / 64, HEADS, BATCH), 128, ASMEM>>>(
        qkh, qkl, vth, vtl, rpb, ath, atl);

    // 4) output projection (fp32 out + bias)
    cudaFuncSetAttribute(mma_gemm<0>, cudaFuncAttributeMaxDynamicSharedMemorySize, GEMM_SMEM);
    mma_gemm<0><<<dim3(DIMSZ / 128, NROWS / 128), 256, GEMM_SMEM>>>(
        ath, atl, woh, wol, bout, out, nullptr, nullptr, DIMSZ);
}